// round 5
// baseline (speedup 1.0000x reference)
#include <cuda_runtime.h>
#include <cstdint>

#define BATCH 32
#define MN    1024
#define DF    128
#define ED    64
#define NROWS (BATCH*MN)   // 32768

// ---------------- device scratch (no runtime allocation allowed) ----------------
__device__ float g_S   [(size_t)BATCH*MN*MN];   // 128 MB: S = relu(E E^T) per graph
__device__ float g_degp[NROWS*32];              // row-sum partials (nt*4 + wx)
__device__ float g_dinv[NROWS];
__device__ float g_z   [(size_t)NROWS*DF];      // Z = dinv ⊙ (In @ W^T), row-major
__device__ float g_y   [(size_t)NROWS*DF];      // layer-1 output

// ---------------- helpers ----------------
__device__ __forceinline__ uint32_t smem_u32(const void* p){
    uint32_t a;
    asm("{ .reg .u64 t; cvta.to.shared.u64 t, %1; cvt.u32.u64 %0, t; }" : "=r"(a) : "l"(p));
    return a;
}
__device__ __forceinline__ void cpa16(uint32_t d, const void* s){
    asm volatile("cp.async.cg.shared.global [%0], [%1], 16;" :: "r"(d), "l"(s));
}
#define CP_COMMIT() asm volatile("cp.async.commit_group;" ::: "memory")
#define CP_WAIT0()  asm volatile("cp.async.wait_group 0;" ::: "memory")
#define CP_WAIT1()  asm volatile("cp.async.wait_group 1;" ::: "memory")

// Dekker-style tf32 split: hi exactly representable in tf32 (low 13 bits zeroed),
// lo = v - hi exact in fp32; HMMA reads only the top 19 bits of each operand.
__device__ __forceinline__ void split(float v, uint32_t& h, uint32_t& l){
    uint32_t u = __float_as_uint(v) & 0xFFFFE000u;
    h = u;
    l = __float_as_uint(v - __uint_as_float(u));
}

__device__ __forceinline__ void mma8(float c[4], const uint32_t a[4], const uint32_t b[2]){
    asm volatile(
        "mma.sync.aligned.m16n8k8.row.col.f32.tf32.tf32.f32 "
        "{%0,%1,%2,%3}, {%4,%5,%6,%7}, {%8,%9}, {%0,%1,%2,%3};"
        : "+f"(c[0]), "+f"(c[1]), "+f"(c[2]), "+f"(c[3])
        : "r"(a[0]), "r"(a[1]), "r"(a[2]), "r"(a[3]), "r"(b[0]), "r"(b[1]));
}

// One k8 step for a 128x128 CTA tile, 8 warps of 64x32 (wy in {0,1}, wx in {0..3}).
// A smem: [m][k] pitch PA.  B smem: BKN ? [k][n] pitch PB : [n][k] pitch PB.
// 3-product tf32 split executed as THREE PASSES over all 16 (i,j) fragments so
// dependent HMMAs on the same accumulator are 16 MMAs apart (chain fully hidden).
template<int PA, int PB, bool BKN>
__device__ __forceinline__ void mma_step(const float* __restrict__ As,
                                         const float* __restrict__ Bs,
                                         int kk, int wy, int wx, int lane,
                                         float c[4][4][4])
{
    const int g = lane >> 2, t = lane & 3;
    uint32_t ah[4][4], al[4][4];
    #pragma unroll
    for (int i = 0; i < 4; i++){
        const float* ap = As + (wy*64 + i*16 + g)*PA + kk + t;
        split(ap[0],        ah[i][0], al[i][0]);
        split(ap[8*PA],     ah[i][1], al[i][1]);
        split(ap[4],        ah[i][2], al[i][2]);
        split(ap[8*PA + 4], ah[i][3], al[i][3]);
    }
    uint32_t bh[4][2], bl[4][2];
    #pragma unroll
    for (int j = 0; j < 4; j++){
        const int n0 = wx*32 + j*8 + g;
        const float* bp = BKN ? (Bs + (size_t)(kk + t)*PB + n0)
                              : (Bs + (size_t)n0*PB + kk + t);
        split(bp[0], bh[j][0], bl[j][0]);
        split(BKN ? bp[4*PB] : bp[4], bh[j][1], bl[j][1]);
    }
    // pass 1: ah * bh
    #pragma unroll
    for (int j = 0; j < 4; j++)
        #pragma unroll
        for (int i = 0; i < 4; i++) mma8(c[i][j], ah[i], bh[j]);
    // pass 2: al * bh
    #pragma unroll
    for (int j = 0; j < 4; j++)
        #pragma unroll
        for (int i = 0; i < 4; i++) mma8(c[i][j], al[i], bh[j]);
    // pass 3: ah * bl
    #pragma unroll
    for (int j = 0; j < 4; j++)
        #pragma unroll
        for (int i = 0; i < 4; i++) mma8(c[i][j], ah[i], bl[j]);
}

// ============================================================================
// Kernel 1: S-build.  S tile = relu(Em En^T), K=64; + row-sum partials.
// grid (8 mt, 8 nt, 32 g), 256 threads.
// ============================================================================
#define SB_PITCH 68
#define SB_TILE  (128*SB_PITCH)          // floats
#define SB_SMEM  (2*SB_TILE*4)           // 69632 B

__global__ void __launch_bounds__(256,2) k_sbuild(const float* __restrict__ E)
{
    extern __shared__ float sm[];
    const uint32_t smb = smem_u32(sm);
    const int tid = threadIdx.x, lane = tid & 31, wid = tid >> 5;
    const int wy = wid >> 2, wx = wid & 3;
    const int mt = blockIdx.x, nt = blockIdx.y, gb = blockIdx.z;

    const float* Emg = E + (size_t)(gb*MN + mt*128)*ED;
    const float* Eng = E + (size_t)(gb*MN + nt*128)*ED;
    // Each tile: 128 rows x 16 float4 = 2048 float4  ->  8 rounds of 256 threads
    #pragma unroll
    for (int r = 0; r < 8; r++){
        int id = r*256 + tid;
        int m = id >> 4, f = id & 15;
        cpa16(smb + m*272 + f*16,               Emg + (size_t)m*ED + f*4);
        cpa16(smb + SB_TILE*4 + m*272 + f*16,   Eng + (size_t)m*ED + f*4);
    }
    CP_COMMIT(); CP_WAIT0();
    __syncthreads();

    float c4[4][4][4] = {};
    #pragma unroll
    for (int kk = 0; kk < 64; kk += 8)
        mma_step<SB_PITCH, SB_PITCH, false>(sm, sm + SB_TILE, kk, wy, wx, lane, c4);

    // epilogue: relu, store S tile, warp-reduced row-sum partials
    const int g = lane >> 2, t = lane & 3;
    const int rowbase = gb*MN + mt*128;
    #pragma unroll
    for (int i = 0; i < 4; i++){
        #pragma unroll
        for (int h = 0; h < 2; h++){
            const int row = rowbase + wy*64 + i*16 + g + h*8;
            float* sr = g_S + (size_t)row*MN + nt*128;
            float rsum = 0.f;
            #pragma unroll
            for (int j = 0; j < 4; j++){
                float v0 = fmaxf(c4[i][j][h*2+0], 0.f);
                float v1 = fmaxf(c4[i][j][h*2+1], 0.f);
                rsum += v0 + v1;
                *(float2*)&sr[wx*32 + j*8 + 2*t] = make_float2(v0, v1);
            }
            rsum += __shfl_xor_sync(0xFFFFFFFFu, rsum, 1);
            rsum += __shfl_xor_sync(0xFFFFFFFFu, rsum, 2);
            if (t == 0) g_degp[row*32 + nt*4 + wx] = rsum;
        }
    }
}

// ============================================================================
// Kernel 2: dinv = rsqrt(1 + sum of 32 partials)
// ============================================================================
__global__ void k_dinv()
{
    const int i = blockIdx.x*256 + threadIdx.x;
    float s = 1.0f;                      // +I in A = adj + I
    #pragma unroll
    for (int j = 0; j < 32; j++) s += g_degp[i*32 + j];
    g_dinv[i] = rsqrtf(s);
}

// ============================================================================
// Kernel 3: Z = dinv ⊙ (In @ W^T).  K=128, 4 chunks of 32, double-buffered.
// grid 256 (128-row tiles), 256 threads.
// ============================================================================
#define GW_PITCH 36
#define GW_TILE  (128*GW_PITCH)          // 4608 floats
#define GW_STAGE (2*GW_TILE)             // A + B
#define GW_SMEM  (2*GW_STAGE*4)          // 73728 B

__global__ void __launch_bounds__(256,2) k_gemmw(const float* __restrict__ xin,
                                                 const float* __restrict__ W,
                                                 int use_internal)
{
    extern __shared__ float sm[];
    const uint32_t smb = smem_u32(sm);
    const float* __restrict__ in = use_internal ? g_y : xin;
    const int tid = threadIdx.x, lane = tid & 31, wid = tid >> 5;
    const int wy = wid >> 2, wx = wid & 3;
    const int rbase = blockIdx.x*128;

    auto copy = [&](int c){
        const uint32_t ab = smb + (uint32_t)(c & 1)*GW_STAGE*4;
        const uint32_t bb = ab + GW_TILE*4;
        #pragma unroll
        for (int r = 0; r < 4; r++){
            int id = r*256 + tid;        // 1024 float4: 128 rows x 8
            int m = id >> 3, f = id & 7;
            cpa16(ab + m*144 + f*16, in + (size_t)(rbase + m)*128 + c*32 + f*4);
            cpa16(bb + m*144 + f*16, W  + (size_t)m*128          + c*32 + f*4);
        }
        CP_COMMIT();
    };

    float c4[4][4][4] = {};
    copy(0);
    for (int c = 0; c < 4; c++){
        if (c < 3){ copy(c + 1); CP_WAIT1(); } else { CP_WAIT0(); }
        __syncthreads();
        const float* As = sm + (c & 1)*GW_STAGE;
        const float* Bs = As + GW_TILE;
        #pragma unroll
        for (int kk = 0; kk < 32; kk += 8)
            mma_step<GW_PITCH, GW_PITCH, false>(As, Bs, kk, wy, wx, lane, c4);
        __syncthreads();
    }

    const int g = lane >> 2, t = lane & 3;
    #pragma unroll
    for (int i = 0; i < 4; i++){
        #pragma unroll
        for (int h = 0; h < 2; h++){
            const int row = rbase + wy*64 + i*16 + g + h*8;
            const float sc = g_dinv[row];
            float* zr = g_z + (size_t)row*128;
            #pragma unroll
            for (int j = 0; j < 4; j++){
                *(float2*)&zr[wx*32 + j*8 + 2*t] =
                    make_float2(sc*c4[i][j][h*2], sc*c4[i][j][h*2+1]);
            }
        }
    }
}

// ============================================================================
// Kernel 4: propagation.  out = relu(dinv_m ⊙ (S@Z + Z_m)).  K=1024, 32 chunks.
// grid (8 mt, 32 g), 256 threads.
// ============================================================================
#define PA_PITCH 36
#define PB_PITCH 132
#define PR_ATILE (128*PA_PITCH)          // 4608 floats
#define PR_BTILE (32*PB_PITCH)           // 4224 floats
#define PR_STAGE (PR_ATILE + PR_BTILE)   // 8832 floats
#define PR_SMEM  (2*PR_STAGE*4)          // 70656 B

__global__ void __launch_bounds__(256,2) k_prop(float* __restrict__ outext, int to_internal)
{
    extern __shared__ float sm[];
    const uint32_t smb = smem_u32(sm);
    const int tid = threadIdx.x, lane = tid & 31, wid = tid >> 5;
    const int wy = wid >> 2, wx = wid & 3;
    const int mt = blockIdx.x, gb = blockIdx.y;
    float* __restrict__ dst = to_internal ? g_y : outext;

    const float* Sbase = g_S + (size_t)(gb*MN + mt*128)*MN;
    const float* Zbase = g_z + (size_t)gb*MN*128;

    auto copy = [&](int c){
        const uint32_t ab = smb + (uint32_t)(c & 1)*PR_STAGE*4;
        const uint32_t bb = ab + PR_ATILE*4;
        #pragma unroll
        for (int r = 0; r < 4; r++){
            int id = r*256 + tid;
            int m = id >> 3, f = id & 7;      // A: 128 rows x 8 float4
            cpa16(ab + m*144 + f*16, Sbase + (size_t)m*MN + c*32 + f*4);
            int n = id >> 5, fb = id & 31;    // B: 32 rows x 32 float4
            cpa16(bb + n*528 + fb*16, Zbase + (size_t)(c*32 + n)*128 + fb*4);
        }
        CP_COMMIT();
    };

    float c4[4][4][4] = {};
    copy(0);
    for (int c = 0; c < 32; c++){
        if (c < 31){ copy(c + 1); CP_WAIT1(); } else { CP_WAIT0(); }
        __syncthreads();
        const float* As = sm + (c & 1)*PR_STAGE;
        const float* Bs = As + PR_ATILE;
        #pragma unroll
        for (int kk = 0; kk < 32; kk += 8)
            mma_step<PA_PITCH, PB_PITCH, true>(As, Bs, kk, wy, wx, lane, c4);
        __syncthreads();
    }

    const int g = lane >> 2, t = lane & 3;
    const int rowbase = gb*MN + mt*128;
    #pragma unroll
    for (int i = 0; i < 4; i++){
        #pragma unroll
        for (int h = 0; h < 2; h++){
            const int row = rowbase + wy*64 + i*16 + g + h*8;
            const float sc = g_dinv[row];
            const float* zr = g_z + (size_t)row*128;
            float* orow = dst + (size_t)row*128;
            #pragma unroll
            for (int j = 0; j < 4; j++){
                const int col = wx*32 + j*8 + 2*t;
                float2 z = *(const float2*)&zr[col];
                float2 o;
                o.x = fmaxf(sc*(c4[i][j][h*2]   + z.x), 0.f);
                o.y = fmaxf(sc*(c4[i][j][h*2+1] + z.y), 0.f);
                *(float2*)&orow[col] = o;
            }
        }
    }
}

// ============================================================================
extern "C" void kernel_launch(void* const* d_in, const int* in_sizes, int n_in,
                              void* d_out, int out_size)
{
    (void)in_sizes; (void)n_in; (void)out_size;
    const float* X  = (const float*)d_in[0];
    const float* E  = (const float*)d_in[1];
    const float* W1 = (const float*)d_in[2];
    const float* W2 = (const float*)d_in[3];
    float* out = (float*)d_out;

    cudaFuncSetAttribute(k_sbuild, cudaFuncAttributeMaxDynamicSharedMemorySize, SB_SMEM);
    cudaFuncSetAttribute(k_gemmw,  cudaFuncAttributeMaxDynamicSharedMemorySize, GW_SMEM);
    cudaFuncSetAttribute(k_prop,   cudaFuncAttributeMaxDynamicSharedMemorySize, PR_SMEM);

    k_sbuild<<<dim3(8, 8, 32), 256, SB_SMEM>>>(E);
    k_dinv  <<<NROWS/256, 256>>>();
    k_gemmw <<<256, 256, GW_SMEM>>>(X, W1, 0);
    k_prop  <<<dim3(8, 32), 256, PR_SMEM>>>(nullptr, 1);
    k_gemmw <<<256, 256, GW_SMEM>>>(nullptr, W2, 1);
    k_prop  <<<dim3(8, 32), 256, PR_SMEM>>>(out, 0);
}

// round 6
// speedup vs baseline: 1.2848x; 1.2848x over previous
#include <cuda_runtime.h>
#include <cuda_bf16.h>
#include <cstdint>

#define BATCH 32
#define MN    1024
#define DF    128
#define ED    64
#define NROWS (BATCH*MN)   // 32768

// ---------------- device scratch (no runtime allocation allowed) ----------------
__device__ __nv_bfloat16 g_Sh[(size_t)BATCH*MN*MN];   // 64 MB: hi plane of S
__device__ __nv_bfloat16 g_Sl[(size_t)BATCH*MN*MN];   // 64 MB: lo plane of S
__device__ float         g_degp[NROWS*32];
__device__ float         g_dinv[NROWS];
__device__ float         g_z  [(size_t)NROWS*DF];     // Z fp32 row-major (identity term)
__device__ __nv_bfloat16 g_zth[(size_t)BATCH*DF*MN];  // Z^T hi plane [g][d][n]
__device__ __nv_bfloat16 g_ztl[(size_t)BATCH*DF*MN];  // Z^T lo plane
__device__ float         g_y  [(size_t)NROWS*DF];     // layer-1 output fp32

// ---------------- helpers ----------------
__device__ __forceinline__ uint32_t smem_u32(const void* p){
    uint32_t a;
    asm("{ .reg .u64 t; cvta.to.shared.u64 t, %1; cvt.u32.u64 %0, t; }" : "=r"(a) : "l"(p));
    return a;
}
__device__ __forceinline__ void cpa16(uint32_t d, const void* s){
    asm volatile("cp.async.cg.shared.global [%0], [%1], 16;" :: "r"(d), "l"(s));
}
#define CP_COMMIT() asm volatile("cp.async.commit_group;" ::: "memory")
#define CP_WAIT0()  asm volatile("cp.async.wait_group 0;" ::: "memory")
#define CP_WAIT1()  asm volatile("cp.async.wait_group 1;" ::: "memory")

// bf16 2-term split of a pair (v0 -> low half, v1 -> high half of each packed reg).
// h = bf16(v), l = bf16(v - f32(h));  v ≈ h + l to ~16 mantissa bits.
__device__ __forceinline__ void bsplit2(float v0, float v1, uint32_t& h01, uint32_t& l01){
    asm("cvt.rn.bf16x2.f32 %0, %1, %2;" : "=r"(h01) : "f"(v1), "f"(v0));
    float h0 = __uint_as_float(h01 << 16);
    float h1 = __uint_as_float(h01 & 0xFFFF0000u);
    float l0 = v0 - h0, l1 = v1 - h1;
    asm("cvt.rn.bf16x2.f32 %0, %1, %2;" : "=r"(l01) : "f"(l1), "f"(l0));
}

__device__ __forceinline__ void mma16(float c[4], const uint32_t a[4], const uint32_t b[2]){
    asm volatile(
        "mma.sync.aligned.m16n8k16.row.col.f32.bf16.bf16.f32 "
        "{%0,%1,%2,%3}, {%4,%5,%6,%7}, {%8,%9}, {%0,%1,%2,%3};"
        : "+f"(c[0]), "+f"(c[1]), "+f"(c[2]), "+f"(c[3])
        : "r"(a[0]), "r"(a[1]), "r"(a[2]), "r"(a[3]), "r"(b[0]), "r"(b[1]));
}

// 3-pass product schedule over all 16 fragments
__device__ __forceinline__ void mma3pass(float c[4][4][4],
    const uint32_t ah[4][4], const uint32_t al[4][4],
    const uint32_t bh[4][2], const uint32_t bl[4][2])
{
    #pragma unroll
    for (int j = 0; j < 4; j++)
        #pragma unroll
        for (int i = 0; i < 4; i++) mma16(c[i][j], ah[i], bh[j]);
    #pragma unroll
    for (int j = 0; j < 4; j++)
        #pragma unroll
        for (int i = 0; i < 4; i++) mma16(c[i][j], al[i], bh[j]);
    #pragma unroll
    for (int j = 0; j < 4; j++)
        #pragma unroll
        for (int i = 0; i < 4; i++) mma16(c[i][j], ah[i], bl[j]);
}

// One k16 step from fp32 smem tiles (A [m][k] pitch PA, B [n][k] pitch PB),
// splitting to bf16 in-register.
template<int PA, int PB>
__device__ __forceinline__ void mma_step_f32(const float* __restrict__ As,
                                             const float* __restrict__ Bs,
                                             int kk, int wy, int wx, int lane,
                                             float c[4][4][4])
{
    const int g = lane >> 2, t = lane & 3;
    uint32_t ah[4][4], al[4][4], bh[4][2], bl[4][2];
    #pragma unroll
    for (int i = 0; i < 4; i++){
        const float* ap = As + (wy*64 + i*16 + g)*PA + kk + 2*t;
        float2 v;
        v = *(const float2*)(ap);            bsplit2(v.x, v.y, ah[i][0], al[i][0]);
        v = *(const float2*)(ap + 8*PA);     bsplit2(v.x, v.y, ah[i][1], al[i][1]);
        v = *(const float2*)(ap + 8);        bsplit2(v.x, v.y, ah[i][2], al[i][2]);
        v = *(const float2*)(ap + 8*PA + 8); bsplit2(v.x, v.y, ah[i][3], al[i][3]);
    }
    #pragma unroll
    for (int j = 0; j < 4; j++){
        const float* bp = Bs + (wx*32 + j*8 + g)*PB + kk + 2*t;
        float2 v;
        v = *(const float2*)(bp);     bsplit2(v.x, v.y, bh[j][0], bl[j][0]);
        v = *(const float2*)(bp + 8); bsplit2(v.x, v.y, bh[j][1], bl[j][1]);
    }
    mma3pass(c, ah, al, bh, bl);
}

// One k16 step from pre-split bf16 planes (A [m][k], B-as-[n][k]; pitch P elems).
template<int P>
__device__ __forceinline__ void mma_step_bf16(const __nv_bfloat16* __restrict__ Ah,
                                              const __nv_bfloat16* __restrict__ Al,
                                              const __nv_bfloat16* __restrict__ Bh,
                                              const __nv_bfloat16* __restrict__ Bl,
                                              int kk, int wy, int wx, int lane,
                                              float c[4][4][4])
{
    const int g = lane >> 2, t = lane & 3;
    uint32_t ah[4][4], al[4][4], bh[4][2], bl[4][2];
    #pragma unroll
    for (int i = 0; i < 4; i++){
        const int r0 = (wy*64 + i*16 + g)*P + kk + 2*t;
        ah[i][0] = *(const uint32_t*)(Ah + r0);
        ah[i][1] = *(const uint32_t*)(Ah + r0 + 8*P);
        ah[i][2] = *(const uint32_t*)(Ah + r0 + 8);
        ah[i][3] = *(const uint32_t*)(Ah + r0 + 8*P + 8);
        al[i][0] = *(const uint32_t*)(Al + r0);
        al[i][1] = *(const uint32_t*)(Al + r0 + 8*P);
        al[i][2] = *(const uint32_t*)(Al + r0 + 8);
        al[i][3] = *(const uint32_t*)(Al + r0 + 8*P + 8);
    }
    #pragma unroll
    for (int j = 0; j < 4; j++){
        const int rb = (wx*32 + j*8 + g)*P + kk + 2*t;
        bh[j][0] = *(const uint32_t*)(Bh + rb);
        bh[j][1] = *(const uint32_t*)(Bh + rb + 8);
        bl[j][0] = *(const uint32_t*)(Bl + rb);
        bl[j][1] = *(const uint32_t*)(Bl + rb + 8);
    }
    mma3pass(c, ah, al, bh, bl);
}

// ============================================================================
// Kernel 1: S-build.  S tile = relu(Em En^T), K=64; writes bf16 hi/lo planes
// + row-sum partials.  grid (8 mt, 8 nt, 32 g), 256 threads.
// ============================================================================
#define SB_PITCH 72                     // 288 B rows: conflict-free for float2 quads
#define SB_TILE  (128*SB_PITCH)
#define SB_SMEM  (2*SB_TILE*4)          // 73728 B

__global__ void __launch_bounds__(256,2) k_sbuild(const float* __restrict__ E)
{
    extern __shared__ float sm[];
    const uint32_t smb = smem_u32(sm);
    const int tid = threadIdx.x, lane = tid & 31, wid = tid >> 5;
    const int wy = wid >> 2, wx = wid & 3;
    const int mt = blockIdx.x, nt = blockIdx.y, gb = blockIdx.z;

    const float* Emg = E + (size_t)(gb*MN + mt*128)*ED;
    const float* Eng = E + (size_t)(gb*MN + nt*128)*ED;
    #pragma unroll
    for (int r = 0; r < 8; r++){
        int id = r*256 + tid;           // 2048 float4 per tile: 128 rows x 16
        int m = id >> 4, f = id & 15;
        cpa16(smb + m*288 + f*16,               Emg + (size_t)m*ED + f*4);
        cpa16(smb + SB_TILE*4 + m*288 + f*16,   Eng + (size_t)m*ED + f*4);
    }
    CP_COMMIT(); CP_WAIT0();
    __syncthreads();

    float c4[4][4][4] = {};
    #pragma unroll
    for (int kk = 0; kk < 64; kk += 16)
        mma_step_f32<SB_PITCH, SB_PITCH>(sm, sm + SB_TILE, kk, wy, wx, lane, c4);

    // epilogue: relu, split-store S planes, warp-reduced row-sum partials
    const int g = lane >> 2, t = lane & 3;
    const int rowbase = gb*MN + mt*128;
    #pragma unroll
    for (int i = 0; i < 4; i++){
        #pragma unroll
        for (int h = 0; h < 2; h++){
            const int row = rowbase + wy*64 + i*16 + g + h*8;
            const size_t soff = (size_t)row*MN + nt*128;
            float rsum = 0.f;
            #pragma unroll
            for (int j = 0; j < 4; j++){
                float v0 = fmaxf(c4[i][j][h*2+0], 0.f);
                float v1 = fmaxf(c4[i][j][h*2+1], 0.f);
                rsum += v0 + v1;
                uint32_t h01, l01;
                bsplit2(v0, v1, h01, l01);
                const size_t o = soff + wx*32 + j*8 + 2*t;
                *(uint32_t*)&g_Sh[o] = h01;
                *(uint32_t*)&g_Sl[o] = l01;
            }
            rsum += __shfl_xor_sync(0xFFFFFFFFu, rsum, 1);
            rsum += __shfl_xor_sync(0xFFFFFFFFu, rsum, 2);
            if (t == 0) g_degp[row*32 + nt*4 + wx] = rsum;
        }
    }
}

// ============================================================================
// Kernel 2: dinv = rsqrt(1 + sum of 32 partials)
// ============================================================================
__global__ void k_dinv()
{
    const int i = blockIdx.x*256 + threadIdx.x;
    float s = 1.0f;
    #pragma unroll
    for (int j = 0; j < 32; j++) s += g_degp[i*32 + j];
    g_dinv[i] = rsqrtf(s);
}

// ============================================================================
// Kernel 3: Z = dinv ⊙ (In @ W^T).  K=128, 4 chunks, double-buffered.
// Writes g_z fp32 + transposed bf16 split planes.  grid 256, 256 threads.
// ============================================================================
#define GW_PITCH 40                     // 160 B rows
#define GW_TILE  (128*GW_PITCH)         // 5120 floats
#define GW_STAGE (2*GW_TILE)
#define GW_SMEM  (2*GW_STAGE*4)         // 81920 B

__global__ void __launch_bounds__(256,2) k_gemmw(const float* __restrict__ xin,
                                                 const float* __restrict__ W,
                                                 int use_internal)
{
    extern __shared__ float sm[];
    const uint32_t smb = smem_u32(sm);
    const float* __restrict__ in = use_internal ? g_y : xin;
    const int tid = threadIdx.x, lane = tid & 31, wid = tid >> 5;
    const int wy = wid >> 2, wx = wid & 3;
    const int rbase = blockIdx.x*128;

    auto copy = [&](int c){
        const uint32_t ab = smb + (uint32_t)(c & 1)*GW_STAGE*4;
        const uint32_t bb = ab + GW_TILE*4;
        #pragma unroll
        for (int r = 0; r < 4; r++){
            int id = r*256 + tid;       // 1024 float4: 128 rows x 8
            int m = id >> 3, f = id & 7;
            cpa16(ab + m*160 + f*16, in + (size_t)(rbase + m)*128 + c*32 + f*4);
            cpa16(bb + m*160 + f*16, W  + (size_t)m*128          + c*32 + f*4);
        }
        CP_COMMIT();
    };

    float c4[4][4][4] = {};
    copy(0);
    for (int c = 0; c < 4; c++){
        if (c < 3){ copy(c + 1); CP_WAIT1(); } else { CP_WAIT0(); }
        __syncthreads();
        const float* As = sm + (c & 1)*GW_STAGE;
        const float* Bs = As + GW_TILE;
        #pragma unroll
        for (int kk = 0; kk < 32; kk += 16)
            mma_step_f32<GW_PITCH, GW_PITCH>(As, Bs, kk, wy, wx, lane, c4);
        __syncthreads();
    }

    const int g = lane >> 2, t = lane & 3;
    #pragma unroll
    for (int i = 0; i < 4; i++){
        #pragma unroll
        for (int h = 0; h < 2; h++){
            const int row = rbase + wy*64 + i*16 + g + h*8;
            const float sc = g_dinv[row];
            const int gb = row >> 10, nloc = row & 1023;
            float* zr = g_z + (size_t)row*128;
            #pragma unroll
            for (int j = 0; j < 4; j++){
                const int col = wx*32 + j*8 + 2*t;
                float v0 = sc*c4[i][j][h*2], v1 = sc*c4[i][j][h*2+1];
                *(float2*)&zr[col] = make_float2(v0, v1);
                // transposed split planes: [g][d][n]
                __nv_bfloat16 h0 = __float2bfloat16(v0);
                __nv_bfloat16 h1 = __float2bfloat16(v1);
                const size_t o0 = ((size_t)gb*DF + col    )*MN + nloc;
                const size_t o1 = ((size_t)gb*DF + col + 1)*MN + nloc;
                g_zth[o0] = h0;  g_ztl[o0] = __float2bfloat16(v0 - __bfloat162float(h0));
                g_zth[o1] = h1;  g_ztl[o1] = __float2bfloat16(v1 - __bfloat162float(h1));
            }
        }
    }
}

// ============================================================================
// Kernel 4: propagation.  out = relu(dinv_m ⊙ (S@Z + Z_m)).  K=1024, 32 chunks.
// All-bf16 pre-split smem tiles: zero split math in hot loop.
// grid (8 mt, 32 g), 256 threads.
// ============================================================================
#define PR_PITCH 40                     // bf16 elems; 80 B rows, conflict-free
#define PR_PLANE (128*PR_PITCH)         // 5120 bf16 = 10240 B
#define PR_STAGE (4*PR_PLANE)           // Sh, Sl, Zth, Ztl
#define PR_SMEM  (2*PR_STAGE*2)         // 81920 B

__global__ void __launch_bounds__(256,2) k_prop(float* __restrict__ outext, int to_internal)
{
    extern __shared__ __nv_bfloat16 smh[];
    const uint32_t smb = smem_u32(smh);
    const int tid = threadIdx.x, lane = tid & 31, wid = tid >> 5;
    const int wy = wid >> 2, wx = wid & 3;
    const int mt = blockIdx.x, gb = blockIdx.y;
    float* __restrict__ dst = to_internal ? g_y : outext;

    const int mrow0 = gb*MN + mt*128;

    auto copy = [&](int c){
        const uint32_t sb = smb + (uint32_t)(c & 1)*PR_STAGE*2;
        #pragma unroll
        for (int r = 0; r < 8; r++){
            int id = r*256 + tid;              // 2048: 4 planes x 128 rows x 4
            int plane = id >> 9, rem = id & 511;
            int row = rem >> 2, f = rem & 3;
            const uint32_t dsta = sb + plane*(PR_PLANE*2) + row*80 + f*16;
            const __nv_bfloat16* src;
            if      (plane == 0) src = g_Sh  + (size_t)(mrow0 + row)*MN + c*32 + f*8;
            else if (plane == 1) src = g_Sl  + (size_t)(mrow0 + row)*MN + c*32 + f*8;
            else if (plane == 2) src = g_zth + ((size_t)gb*DF + row)*MN + c*32 + f*8;
            else                 src = g_ztl + ((size_t)gb*DF + row)*MN + c*32 + f*8;
            cpa16(dsta, src);
        }
        CP_COMMIT();
    };

    float c4[4][4][4] = {};
    copy(0);
    for (int c = 0; c < 32; c++){
        if (c < 31){ copy(c + 1); CP_WAIT1(); } else { CP_WAIT0(); }
        __syncthreads();
        const __nv_bfloat16* Ah = smh + (size_t)(c & 1)*PR_STAGE;
        const __nv_bfloat16* Al = Ah + PR_PLANE;
        const __nv_bfloat16* Bh = Ah + 2*PR_PLANE;
        const __nv_bfloat16* Bl = Ah + 3*PR_PLANE;
        #pragma unroll
        for (int kk = 0; kk < 32; kk += 16)
            mma_step_bf16<PR_PITCH>(Ah, Al, Bh, Bl, kk, wy, wx, lane, c4);
        __syncthreads();
    }

    const int g = lane >> 2, t = lane & 3;
    #pragma unroll
    for (int i = 0; i < 4; i++){
        #pragma unroll
        for (int h = 0; h < 2; h++){
            const int row = mrow0 + wy*64 + i*16 + g + h*8;
            const float sc = g_dinv[row];
            const float* zr = g_z + (size_t)row*128;
            float* orow = dst + (size_t)row*128;
            #pragma unroll
            for (int j = 0; j < 4; j++){
                const int col = wx*32 + j*8 + 2*t;
                float2 z = *(const float2*)&zr[col];
                float2 o;
                o.x = fmaxf(sc*(c4[i][j][h*2]   + z.x), 0.f);
                o.y = fmaxf(sc*(c4[i][j][h*2+1] + z.y), 0.f);
                *(float2*)&orow[col] = o;
            }
        }
    }
}

// ============================================================================
extern "C" void kernel_launch(void* const* d_in, const int* in_sizes, int n_in,
                              void* d_out, int out_size)
{
    (void)in_sizes; (void)n_in; (void)out_size;
    const float* X  = (const float*)d_in[0];
    const float* E  = (const float*)d_in[1];
    const float* W1 = (const float*)d_in[2];
    const float* W2 = (const float*)d_in[3];
    float* out = (float*)d_out;

    cudaFuncSetAttribute(k_sbuild, cudaFuncAttributeMaxDynamicSharedMemorySize, SB_SMEM);
    cudaFuncSetAttribute(k_gemmw,  cudaFuncAttributeMaxDynamicSharedMemorySize, GW_SMEM);
    cudaFuncSetAttribute(k_prop,   cudaFuncAttributeMaxDynamicSharedMemorySize, PR_SMEM);

    k_sbuild<<<dim3(8, 8, 32), 256, SB_SMEM>>>(E);
    k_dinv  <<<NROWS/256, 256>>>();
    k_gemmw <<<256, 256, GW_SMEM>>>(X, W1, 0);
    k_prop  <<<dim3(8, 32), 256, PR_SMEM>>>(nullptr, 1);
    k_gemmw <<<256, 256, GW_SMEM>>>(nullptr, W2, 1);
    k_prop  <<<dim3(8, 32), 256, PR_SMEM>>>(out, 0);
}